// round 7
// baseline (speedup 1.0000x reference)
#include <cuda_runtime.h>

// Problem constants (match reference)
#define N_ATOMS   245760
#define N_PAIRS   16777216
#define N_MOLS    4096
#define KE_CONST  138.96f

// ---------------------------------------------------------------------------
// Kernel 1: initialize output with per_system_energy * KE
// ---------------------------------------------------------------------------
__global__ void init_out_kernel(const float* __restrict__ pse,
                                float* __restrict__ out) {
    int m = blockIdx.x * blockDim.x + threadIdx.x;
    if (m < N_MOLS) out[m] = pse[m] * KE_CONST;
}

// ---------------------------------------------------------------------------
// chi(d) with the phi(2d) attenuation folded in
// ---------------------------------------------------------------------------
__device__ __forceinline__ float chi_of_d(float d) {
    // phi(u) = 1 - 6u^5 + 15u^4 - 10u^3, u = 2d, zero for u >= 1
    float u  = 2.0f * d;
    float u2 = u * u;
    float u3 = u2 * u;
    float inner = fmaf(-6.0f, u2, fmaf(15.0f, u, -10.0f));
    float phi   = fmaf(u3, inner, 1.0f);
    phi = (u < 1.0f) ? phi : 0.0f;

    float rs = rsqrtf(fmaf(d, d, 1.0f));   // 1/sqrt(d^2+1)
    float rd = __fdividef(1.0f, d);        // 1/d
    return fmaf(phi, rs - rd, rd);         // rd + phi*(rs-rd)
}

// ---------------------------------------------------------------------------
// Kernel 2: main pair loop — R1 structure, 2-wave grid for tail backfill
// ---------------------------------------------------------------------------
__global__ __launch_bounds__(512, 4)
void coulomb_pairs_kernel(const float* __restrict__ q,
                          const int*   __restrict__ idx_i,
                          const int*   __restrict__ idx_j,
                          const float* __restrict__ d_ij,
                          const int*   __restrict__ seg,
                          float*       __restrict__ out)
{
    __shared__ float acc[N_MOLS];   // 16 KB per-block private histogram

    // Vectorized zero (2 x STS.128 per thread)
    {
        float4* acc4 = reinterpret_cast<float4*>(acc);
        for (int m = threadIdx.x; m < N_MOLS / 4; m += blockDim.x)
            acc4[m] = make_float4(0.0f, 0.0f, 0.0f, 0.0f);
    }
    __syncthreads();

    const int nquads = N_PAIRS / 4;
    const int stride = gridDim.x * blockDim.x;

    for (int t = blockIdx.x * blockDim.x + threadIdx.x; t < nquads; t += stride) {
        // ---- Streaming loads (evict-first: keep L1 for gathers) ----
        int4   vi = __ldcs(reinterpret_cast<const int4*>(idx_i) + t);
        int4   vj = __ldcs(reinterpret_cast<const int4*>(idx_j) + t);
        float4 vd = __ldcs(reinterpret_cast<const float4*>(d_ij) + t);
        int4   vs = __ldcs(reinterpret_cast<const int4*>(seg)   + t);

        // ---- Batch the 8 random gathers back-to-back (max MLP) ----
        float qi0 = __ldg(q + vi.x), qj0 = __ldg(q + vj.x);
        float qi1 = __ldg(q + vi.y), qj1 = __ldg(q + vj.y);
        float qi2 = __ldg(q + vi.z), qj2 = __ldg(q + vj.z);
        float qi3 = __ldg(q + vi.w), qj3 = __ldg(q + vj.w);

        // ---- Compute ----
        float c0 = qi0 * qj0 * chi_of_d(vd.x);
        float c1 = qi1 * qj1 * chi_of_d(vd.y);
        float c2 = qi2 * qj2 * chi_of_d(vd.z);
        float c3 = qi3 * qj3 * chi_of_d(vd.w);

        // ---- Scatter: single-statement if -> @P ATOMS (no BSSY) ----
        if (vi.x < vj.x) atomicAdd(&acc[vs.x], c0);
        if (vi.y < vj.y) atomicAdd(&acc[vs.y], c1);
        if (vi.z < vj.z) atomicAdd(&acc[vs.z], c2);
        if (vi.w < vj.w) atomicAdd(&acc[vs.w], c3);
    }

    __syncthreads();

    // Flush block-private histogram (out already holds pse*KE)
    for (int m = threadIdx.x; m < N_MOLS; m += blockDim.x) {
        float v = acc[m];
        if (v != 0.0f)
            atomicAdd(&out[m], v * KE_CONST);
    }
}

// ---------------------------------------------------------------------------
// Launch
// ---------------------------------------------------------------------------
extern "C" void kernel_launch(void* const* d_in, const int* in_sizes, int n_in,
                              void* d_out, int out_size) {
    const float* q    = (const float*)d_in[0];           // per_atom_charge [N_ATOMS]
    const int*   pidx = (const int*)  d_in[1];           // pair_indices [2, N_PAIRS]
    const float* dij  = (const float*)d_in[2];           // d_ij [N_PAIRS]
    const int*   seg  = (const int*)  d_in[3];           // atomic_subsystem_indices [N_PAIRS]
    const float* pse  = (const float*)d_in[4];           // per_system_energy [N_MOLS]
    float* out = (float*)d_out;

    const int* idx_i = pidx;
    const int* idx_j = pidx + N_PAIRS;

    init_out_kernel<<<(N_MOLS + 255) / 256, 256>>>(pse, out);

    // 2 waves of 4 blocks/SM x 148 SMs: wave-2 CTAs backfill SMs that finish
    // wave 1 early, halving the between-SM variance tail.
    const int blocks  = 1184;
    const int threads = 512;
    coulomb_pairs_kernel<<<blocks, threads>>>(q, idx_i, idx_j, dij, seg, out);
}